// round 13
// baseline (speedup 1.0000x reference)
#include <cuda_runtime.h>
#include <cuda_fp16.h>
#include <cstdint>
#include <cstddef>

#define BB   8
#define NN   4096
#define KK   32
#define DD   64
#define CIN  67
#define MLPC 64
#define P1C  128
#define P2C  64
#define R2   0.04f
#define EPSF 1e-5f

// Scratch (device globals; no allocation allowed)
__device__ __half  Th_g[BB * NN * MLPC];   // fp16 s*(pts·Wd + xyz·Wx + b), 128B rows
__device__ float4  P4_g[BB * NN];          // (x, y, z, ||p||^2)
__device__ float   np_g[BB * NN * MLPC];   // max-pooled features, n-major rows
__device__ float4  sC4_g[MLPC];            // {s*Wx0, s*Wx1, s*Wx2, bt - s*rm}
__device__ float   Wt_g[CIN * MLPC];       // s-folded W, [c][o] layout
__device__ float   bs_g[MLPC];             // s*b
__device__ float   W1t_g[P2C * P1C];       // s1-folded W1^T: [c][o] (64 x 128)
__device__ float   W2t_g[P1C * P2C];       // s2-folded W2^T: [o1][o2] (128 x 64)
__device__ float   t1_g[P1C];              // s1*(b1-rm1)+bt1
__device__ float   t2_g[P2C];              // s2*(b2-rm2)+bt2

// ---- f32x2 packed helpers -------------------------------------------------
__device__ __forceinline__ void ffma2(unsigned long long& d,
                                      unsigned long long a,
                                      unsigned long long b) {
    asm("fma.rn.f32x2 %0, %1, %2, %0;" : "+l"(d) : "l"(a), "l"(b));
}
__device__ __forceinline__ unsigned long long pack2(float lo, float hi) {
    unsigned long long r;
    asm("mov.b64 %0, {%1, %2};" : "=l"(r) : "f"(lo), "f"(hi));
    return r;
}
__device__ __forceinline__ void unpack2(unsigned long long p, float& lo, float& hi) {
    asm("mov.b64 {%0, %1}, %2;" : "=f"(lo), "=f"(hi) : "l"(p));
}

// ---------------------------------------------------------------------------
// K0: one-time weight prep for all layers (folded + transposed, coalesced)
// ---------------------------------------------------------------------------
__global__ __launch_bounds__(256) void k_wprep(
    const float* __restrict__ W,   const float* __restrict__ bcv,
    const float* __restrict__ g,   const float* __restrict__ bt,
    const float* __restrict__ rm,  const float* __restrict__ rv,
    const float* __restrict__ W1,  const float* __restrict__ b1,
    const float* __restrict__ g1,  const float* __restrict__ bt1,
    const float* __restrict__ rm1, const float* __restrict__ rv1,
    const float* __restrict__ W2,  const float* __restrict__ b2,
    const float* __restrict__ g2,  const float* __restrict__ bt2,
    const float* __restrict__ rm2, const float* __restrict__ rv2)
{
    int gid = blockIdx.x * 256 + threadIdx.x;

    if (gid < CIN * MLPC) {
        int o = gid & 63, c = gid >> 6;
        float s = g[o] / sqrtf(rv[o] + EPSF);
        Wt_g[gid] = s * W[o * CIN + c];
    }
    if (gid < P2C * P1C) {
        int o = gid & 127, c = gid >> 7;
        float s1 = g1[o] / sqrtf(rv1[o] + EPSF);
        W1t_g[gid] = s1 * W1[o * P2C + c];
    }
    if (gid < P1C * P2C) {
        int o2 = gid & 63, o1 = gid >> 6;
        float s2 = g2[o2] / sqrtf(rv2[o2] + EPSF);
        W2t_g[gid] = s2 * W2[o2 * P1C + o1];
    }
    if (gid < P1C) {
        float s1 = g1[gid] / sqrtf(rv1[gid] + EPSF);
        t1_g[gid] = fmaf(s1, b1[gid] - rm1[gid], bt1[gid]);
    }
    if (gid < P2C) {
        float s2 = g2[gid] / sqrtf(rv2[gid] + EPSF);
        t2_g[gid] = fmaf(s2, b2[gid] - rm2[gid], bt2[gid]);
    }
    if (gid < MLPC) {
        int o = gid;
        float s = g[o] / sqrtf(rv[o] + EPSF);
        bs_g[o] = s * bcv[o];
        sC4_g[o] = make_float4(s * W[o * CIN + 64],
                               s * W[o * CIN + 65],
                               s * W[o * CIN + 66],
                               bt[o] - s * rm[o]);
    }
}

// ---------------------------------------------------------------------------
// K1: Th = X @ Wt, register-tiled GEMM, fp16 output. Pipelined c-loop.
// Block = 128 thr, 64 points; thread = 4 pts x 8 o.
// ---------------------------------------------------------------------------
__global__ __launch_bounds__(128) void k_pre(
    const float* __restrict__ xyz, const float* __restrict__ pts)
{
    __shared__ float Wsh[CIN * MLPC];   // [c][o]  16.75 KB
    __shared__ float Xs[CIN * 64];      // [c][m]  16.75 KB

    int tid = threadIdx.x;

    {
        const float4* src = (const float4*)Wt_g;
        float4* dst = (float4*)Wsh;
        for (int i = tid; i < CIN * MLPC / 4; i += 128) dst[i] = src[i];
    }

    int b  = blockIdx.x >> 6;              // 64 blocks per batch
    int m0 = (blockIdx.x & 63) << 6;       // 64 pts per block

    for (int i = tid; i < CIN * 16; i += 128) {
        int c = i >> 4, j = (i & 15) << 2;
        const float* src = (c < DD) ? &pts[((b << 6) + c) * NN + m0 + j]
                                    : &xyz[(b * 3 + (c - DD)) * NN + m0 + j];
        *(float4*)&Xs[c * 64 + j] = *(const float4*)src;
    }
    __syncthreads();

    if (tid < 64) {
        float x = Xs[64 * 64 + tid], y = Xs[65 * 64 + tid], z = Xs[66 * 64 + tid];
        P4_g[b * NN + m0 + tid] = make_float4(x, y, z, fmaf(z, z, fmaf(y, y, x * x)));
    }

    int om = tid & 7;        // o-base = om*8
    int pm = tid >> 3;       // pt-base = pm*4

    unsigned long long acc[4][4];   // [pt][o-pair]
#pragma unroll
    for (int p = 0; p < 4; p++)
#pragma unroll
        for (int q = 0; q < 4; q++) acc[p][q] = 0ull;

    const float* wp = &Wsh[om * 8];
    const float* xp = &Xs[pm * 4];

    // software-pipelined: prefetch c+1 before computing c
    ulonglong2 wa = *(const ulonglong2*)(wp);
    ulonglong2 wb = *(const ulonglong2*)(wp + 4);
    float4     xv = *(const float4*)(xp);

#pragma unroll 2
    for (int c = 0; c < CIN; c++) {
        ulonglong2 cwa = wa, cwb = wb;
        float4 cxv = xv;
        int cn = (c + 1 < CIN) ? c + 1 : c;
        wa = *(const ulonglong2*)(wp + cn * MLPC);
        wb = *(const ulonglong2*)(wp + cn * MLPC + 4);
        xv = *(const float4*)(xp + cn * 64);

        unsigned long long wv[4] = { cwa.x, cwa.y, cwb.x, cwb.y };
        float xs[4] = { cxv.x, cxv.y, cxv.z, cxv.w };
#pragma unroll
        for (int p = 0; p < 4; p++) {
            unsigned long long xx = pack2(xs[p], xs[p]);
#pragma unroll
            for (int q = 0; q < 4; q++) ffma2(acc[p][q], wv[q], xx);
        }
    }

    float4 bsA = __ldg((const float4*)&bs_g[om * 8]);
    float4 bsB = __ldg((const float4*)&bs_g[om * 8 + 4]);
    float bsv[8] = { bsA.x, bsA.y, bsA.z, bsA.w, bsB.x, bsB.y, bsB.z, bsB.w };

#pragma unroll
    for (int p = 0; p < 4; p++) {
        int gm = b * NN + m0 + pm * 4 + p;
        union { __half2 h2[4]; uint4 u4; } cvt;
#pragma unroll
        for (int q = 0; q < 4; q++) {
            float lo, hi;
            unpack2(acc[p][q], lo, hi);
            cvt.h2[q] = __floats2half2_rn(lo + bsv[2 * q], hi + bsv[2 * q + 1]);
        }
        *((uint4*)Th_g + (size_t)gm * 8 + om) = cvt.u4;
    }
}

// ---------------------------------------------------------------------------
// K2: warp-autonomous ball query + fp16 gather-max (unchanged, R8-proven)
// ---------------------------------------------------------------------------
__global__ __launch_bounds__(256) void k_ball()
{
    __shared__ int gi_sh[8][KK];

    int tid  = threadIdx.x;
    int w    = tid >> 5;
    int lane = tid & 31;
    unsigned below = (1u << lane) - 1u;

    int b  = blockIdx.x >> 9;
    int n  = ((blockIdx.x & 511) << 3) + w;
    int bN = b * NN;

    float4 q = P4_g[bN + n];

    int cnt = 0;
#pragma unroll 1
    for (int base = 0; base < NN; base += 64) {
        float4 c0 = __ldg(&P4_g[bN + base + lane]);
        float4 c1 = __ldg(&P4_g[bN + base + 32 + lane]);

        float d0 = q.w + c0.w - 2.0f * fmaf(q.z, c0.z, fmaf(q.y, c0.y, q.x * c0.x));
        float d1 = q.w + c1.w - 2.0f * fmaf(q.z, c1.z, fmaf(q.y, c1.y, q.x * c1.x));

        unsigned m0 = __ballot_sync(0xffffffffu, d0 <= R2);
        unsigned m1 = __ballot_sync(0xffffffffu, d1 <= R2);

        if (d0 <= R2) {
            int pos = cnt + __popc(m0 & below);
            if (pos < KK) gi_sh[w][pos] = base + lane;
        }
        int n0 = __popc(m0);
        if (d1 <= R2) {
            int pos = cnt + n0 + __popc(m1 & below);
            if (pos < KK) gi_sh[w][pos] = base + 32 + lane;
        }
        cnt += n0 + __popc(m1);
        if (cnt >= KK) break;
    }
    __syncwarp();

    int cap   = (cnt < KK) ? cnt : KK;
    int gidx0 = gi_sh[w][0];

    __half2 mx = __float2half2_rn(-65504.0f);
#pragma unroll
    for (int j = 0; j < KK; j++) {
        int gj = (j < cap) ? gi_sh[w][j] : gidx0;
        const __half2* tr = ((const __half2*)Th_g) + (((size_t)(bN + gj)) << 5) + lane;
        mx = __hmax2(mx, __ldg(tr));
    }
    float2 m = __half22float2(mx);

    float4 a0 = sC4_g[2 * lane];
    float4 a1 = sC4_g[2 * lane + 1];
    float u0 = a0.w - fmaf(a0.z, q.z, fmaf(a0.y, q.y, a0.x * q.x));
    float u1 = a1.w - fmaf(a1.z, q.z, fmaf(a1.y, q.y, a1.x * q.x));

    float2 outv = make_float2(fmaxf(m.x + u0, 0.0f), fmaxf(m.y + u1, 0.0f));
    *(float2*)&np_g[((size_t)(bN + n)) * MLPC + 2 * lane] = outv;
}

// ---------------------------------------------------------------------------
// K3: resnet 64->128->64 + residual ReLU, two-phase tiled GEMM, pipelined.
// Block = 256 thr, 128 points. smem (66.5 KB):
//   [0,8192)      W1T [k][o]          --+ overlapped later by
//   [8192,16640)  Vt  [k][pt] (64x132)--+ X1 [o1][pt] at [0,16384)
// Phase-2 weights streamed via __ldg (L1-resident, broadcast lines).
// ---------------------------------------------------------------------------
__global__ __launch_bounds__(256) void k_resnet(
    const float* __restrict__ pts, float* __restrict__ out)
{
    extern __shared__ float sm[];
    float* W1sh = sm;            // 8192 floats
    float* Vt   = sm + 8192;     // 64 x 132 = 8448 floats
    float* X1   = sm;            // 128 x 128 = 16384 floats (reuse)

    int tid = threadIdx.x;
    int m0  = blockIdx.x << 7;          // 128 points per block
    int b   = m0 >> 12;
    int n0  = m0 & (NN - 1);

    for (int i = tid; i < 2048; i += 256)
        ((float4*)W1sh)[i] = ((const float4*)W1t_g)[i];
    for (int i = tid; i < 2048; i += 256) {
        int pt = i >> 4, c4 = (i & 15) << 2;
        float4 v = *(const float4*)&np_g[(size_t)(m0 + pt) * MLPC + c4];
        Vt[(c4 + 0) * 132 + pt] = v.x;
        Vt[(c4 + 1) * 132 + pt] = v.y;
        Vt[(c4 + 2) * 132 + pt] = v.z;
        Vt[(c4 + 3) * 132 + pt] = v.w;
    }
    __syncthreads();

    int og = tid >> 4;      // 16 groups: o-base = og*8
    int pm = tid & 15;      // pt-base = pm*8 (4 pairs)

    // ---- Phase 1: H[o][pt] = sum_k W1T[k][o] * Vt[k][pt] (pipelined) ----
    unsigned long long acc1[8][4];      // [o][pt-pair]
#pragma unroll
    for (int o = 0; o < 8; o++)
#pragma unroll
        for (int p = 0; p < 4; p++) acc1[o][p] = 0ull;

    {
        const float* wrow = W1sh + og * 8;
        const float* vrow = Vt + pm * 8;

        float4 wa = *(const float4*)(wrow);
        float4 wb = *(const float4*)(wrow + 4);
        ulonglong2 va = *(const ulonglong2*)(vrow);
        ulonglong2 vb = *(const ulonglong2*)(vrow + 4);

#pragma unroll 2
        for (int k = 0; k < P2C; k++) {
            float4 cwa = wa, cwb = wb;
            ulonglong2 cva = va, cvb = vb;
            int kn = (k + 1 < P2C) ? k + 1 : k;
            wa = *(const float4*)(wrow + kn * P1C);
            wb = *(const float4*)(wrow + kn * P1C + 4);
            va = *(const ulonglong2*)(vrow + kn * 132);
            vb = *(const ulonglong2*)(vrow + kn * 132 + 4);

            unsigned long long vp[4] = { cva.x, cva.y, cvb.x, cvb.y };
            float ws[8] = { cwa.x, cwa.y, cwa.z, cwa.w,
                            cwb.x, cwb.y, cwb.z, cwb.w };
#pragma unroll
            for (int o = 0; o < 8; o++) {
                unsigned long long ww = pack2(ws[o], ws[o]);
#pragma unroll
                for (int p = 0; p < 4; p++) ffma2(acc1[o][p], ww, vp[p]);
            }
        }
    }
    __syncthreads();   // phase-1 reads complete before X1 overwrite

    // X1 epilogue: X1[o][pt] = relu(h + t1), stored as pairs
#pragma unroll
    for (int o = 0; o < 8; o++) {
        int oo = og * 8 + o;
        float t1v = __ldg(&t1_g[oo]);
#pragma unroll
        for (int p = 0; p < 4; p++) {
            float lo, hi;
            unpack2(acc1[o][p], lo, hi);
            lo = fmaxf(lo + t1v, 0.0f);
            hi = fmaxf(hi + t1v, 0.0f);
            *(unsigned long long*)&X1[oo * P1C + pm * 8 + 2 * p] = pack2(lo, hi);
        }
    }
    __syncthreads();

    // ---- Phase 2: out[o2][pt] = relu(sum_k W2T[k][o2]*X1[k][pt] + t2 + pts) ----
    int og2 = tid >> 4;     // o2-base = og2*4

    unsigned long long acc2[4][4];      // [o2][pt-pair]
#pragma unroll
    for (int o = 0; o < 4; o++)
#pragma unroll
        for (int p = 0; p < 4; p++) acc2[o][p] = 0ull;

    {
        const float* wrow = W2t_g + og2 * 4;   // global, L1-resident
        const float* xrow = X1 + pm * 8;

        float4 w = __ldg((const float4*)(wrow));
        ulonglong2 xa = *(const ulonglong2*)(xrow);
        ulonglong2 xb = *(const ulonglong2*)(xrow + 4);

#pragma unroll 2
        for (int k = 0; k < P1C; k++) {
            float4 cw = w;
            ulonglong2 cxa = xa, cxb = xb;
            int kn = (k + 1 < P1C) ? k + 1 : k;
            w  = __ldg((const float4*)(wrow + kn * P2C));
            xa = *(const ulonglong2*)(xrow + kn * P1C);
            xb = *(const ulonglong2*)(xrow + kn * P1C + 4);

            unsigned long long xp[4] = { cxa.x, cxa.y, cxb.x, cxb.y };
            float ws[4] = { cw.x, cw.y, cw.z, cw.w };
#pragma unroll
            for (int o = 0; o < 4; o++) {
                unsigned long long ww = pack2(ws[o], ws[o]);
#pragma unroll
                for (int p = 0; p < 4; p++) ffma2(acc2[o][p], ww, xp[p]);
            }
        }
    }

#pragma unroll
    for (int o = 0; o < 4; o++) {
        int o2 = og2 * 4 + o;
        float t2v = __ldg(&t2_g[o2]);
        size_t goff = ((size_t)(b * P2C + o2)) * NN + n0 + pm * 8;
#pragma unroll
        for (int p = 0; p < 4; p++) {
            float2 pv = *(const float2*)&pts[goff + 2 * p];
            float lo, hi;
            unpack2(acc2[o][p], lo, hi);
            lo = fmaxf(lo + t2v + pv.x, 0.0f);
            hi = fmaxf(hi + t2v + pv.y, 0.0f);
            *(float2*)&out[goff + 2 * p] = make_float2(lo, hi);
        }
    }
}

// ---------------------------------------------------------------------------
// Launch
// ---------------------------------------------------------------------------
extern "C" void kernel_launch(void* const* d_in, const int* in_sizes, int n_in,
                              void* d_out, int out_size)
{
    (void)n_in; (void)out_size;

    const float* xyz = (const float*)d_in[0];
    const float* pts = (const float*)d_in[1];
    const float* W   = (const float*)d_in[2];
    const float* bcv = (const float*)d_in[3];
    const float* g   = (const float*)d_in[4];
    const float* bt  = (const float*)d_in[5];
    const float* rm  = (const float*)d_in[6];
    const float* rv  = (const float*)d_in[7];
    const float* W1  = (const float*)d_in[8];
    const float* b1  = (const float*)d_in[9];
    const float* g1  = (const float*)d_in[10];
    const float* bt1 = (const float*)d_in[11];
    const float* rm1 = (const float*)d_in[12];
    const float* rv1 = (const float*)d_in[13];
    const float* W2  = (const float*)d_in[14];
    const float* b2  = (const float*)d_in[15];
    const float* g2  = (const float*)d_in[16];
    const float* bt2 = (const float*)d_in[17];
    const float* rm2 = (const float*)d_in[18];
    const float* rv2 = (const float*)d_in[19];

    float* out = (float*)d_out;

    static const size_t smem3 = 16640 * sizeof(float);   // 66560 B
    cudaFuncSetAttribute(k_resnet, cudaFuncAttributeMaxDynamicSharedMemorySize,
                         (int)smem3);

    cudaMemcpyAsync(out, xyz, (size_t)in_sizes[0] * sizeof(float),
                    cudaMemcpyDeviceToDevice, 0);

    k_wprep<<<32, 256>>>(W, bcv, g, bt, rm, rv,
                         W1, b1, g1, bt1, rm1, rv1,
                         W2, b2, g2, bt2, rm2, rv2);
    k_pre<<<(BB * NN) / 64, 128>>>(xyz, pts);
    k_ball<<<(BB * NN) / 8, 256>>>();
    k_resnet<<<(BB * NN) / 128, 256, smem3>>>(pts, out + in_sizes[0]);
}

// round 15
// speedup vs baseline: 1.3605x; 1.3605x over previous
#include <cuda_runtime.h>
#include <cuda_fp16.h>
#include <cstdint>
#include <cstddef>

#define BB   8
#define NN   4096
#define KK   32
#define DD   64
#define CIN  67
#define MLPC 64
#define P1C  128
#define P2C  64
#define R2   0.04f
#define EPSF 1e-5f

// Scratch (device globals; no allocation allowed)
__device__ __half  Th_g[BB * NN * MLPC];   // fp16 s*(pts·Wd + xyz·Wx + b), 128B rows
__device__ float4  P4_g[BB * NN];          // (x, y, z, ||p||^2)
__device__ float   np_g[BB * NN * MLPC];   // max-pooled features, n-major rows
__device__ float4  sC4_g[MLPC];            // {s*Wx0, s*Wx1, s*Wx2, bt - s*rm}
__device__ float   Wt_g[CIN * MLPC];       // s-folded W, [c][o] layout
__device__ float   bs_g[MLPC];             // s*b
__device__ float   t1_g[P1C];              // s1*(b1-rm1)+bt1
__device__ float   t2_g[P2C];              // s2*(b2-rm2)+bt2
__device__ __half  W1f16_g[P1C * P2C];     // s1-folded W1, fp16, [o:128][k:64]
__device__ __half  W2f16_g[P2C * P1C];     // s2-folded W2, fp16, [o2:64][k:128]

// ---- f32x2 packed helpers (k_pre) ----------------------------------------
__device__ __forceinline__ void ffma2(unsigned long long& d,
                                      unsigned long long a,
                                      unsigned long long b) {
    asm("fma.rn.f32x2 %0, %1, %2, %0;" : "+l"(d) : "l"(a), "l"(b));
}
__device__ __forceinline__ unsigned long long pack2(float lo, float hi) {
    unsigned long long r;
    asm("mov.b64 %0, {%1, %2};" : "=l"(r) : "f"(lo), "f"(hi));
    return r;
}
__device__ __forceinline__ void unpack2(unsigned long long p, float& lo, float& hi) {
    asm("mov.b64 {%0, %1}, %2;" : "=f"(lo), "=f"(hi) : "l"(p));
}

// ---- mma.sync helpers -----------------------------------------------------
__device__ __forceinline__ uint32_t smem_u32(const void* p) {
    uint32_t a;
    asm("{ .reg .u64 t; cvta.to.shared.u64 t, %1; cvt.u32.u64 %0, t; }"
        : "=r"(a) : "l"(p));
    return a;
}
__device__ __forceinline__ void ldsm_x4(uint32_t& r0, uint32_t& r1,
                                        uint32_t& r2, uint32_t& r3, uint32_t addr) {
    asm volatile("ldmatrix.sync.aligned.m8n8.x4.shared.b16 {%0,%1,%2,%3}, [%4];"
                 : "=r"(r0), "=r"(r1), "=r"(r2), "=r"(r3) : "r"(addr));
}
__device__ __forceinline__ void mma16816(float* c, const uint32_t* a,
                                         const uint32_t* b) {
    asm volatile(
        "mma.sync.aligned.m16n8k16.row.col.f32.f16.f16.f32 "
        "{%0,%1,%2,%3}, {%4,%5,%6,%7}, {%8,%9}, {%0,%1,%2,%3};"
        : "+f"(c[0]), "+f"(c[1]), "+f"(c[2]), "+f"(c[3])
        : "r"(a[0]), "r"(a[1]), "r"(a[2]), "r"(a[3]), "r"(b[0]), "r"(b[1]));
}

// ---------------------------------------------------------------------------
// K0: one-time weight prep (folded; fp16 row-major images for mma path)
// ---------------------------------------------------------------------------
__global__ __launch_bounds__(256) void k_wprep(
    const float* __restrict__ W,   const float* __restrict__ bcv,
    const float* __restrict__ g,   const float* __restrict__ bt,
    const float* __restrict__ rm,  const float* __restrict__ rv,
    const float* __restrict__ W1,  const float* __restrict__ b1,
    const float* __restrict__ g1,  const float* __restrict__ bt1,
    const float* __restrict__ rm1, const float* __restrict__ rv1,
    const float* __restrict__ W2,  const float* __restrict__ b2,
    const float* __restrict__ g2,  const float* __restrict__ bt2,
    const float* __restrict__ rm2, const float* __restrict__ rv2)
{
    int gid = blockIdx.x * 256 + threadIdx.x;

    if (gid < CIN * MLPC) {
        int o = gid & 63, c = gid >> 6;
        float s = g[o] / sqrtf(rv[o] + EPSF);
        Wt_g[gid] = s * W[o * CIN + c];
    }
    if (gid < P1C * P2C) {                 // W1 fp16: [o:128][k:64]
        int o = gid >> 6, k = gid & 63;
        float s1 = g1[o] / sqrtf(rv1[o] + EPSF);
        W1f16_g[gid] = __float2half(s1 * W1[o * P2C + k]);
    }
    if (gid < P2C * P1C) {                 // W2 fp16: [o2:64][k:128]
        int o2 = gid >> 7, k = gid & 127;
        float s2 = g2[o2] / sqrtf(rv2[o2] + EPSF);
        W2f16_g[gid] = __float2half(s2 * W2[o2 * P1C + k]);
    }
    if (gid < P1C) {
        float s1 = g1[gid] / sqrtf(rv1[gid] + EPSF);
        t1_g[gid] = fmaf(s1, b1[gid] - rm1[gid], bt1[gid]);
    }
    if (gid < P2C) {
        float s2 = g2[gid] / sqrtf(rv2[gid] + EPSF);
        t2_g[gid] = fmaf(s2, b2[gid] - rm2[gid], bt2[gid]);
    }
    if (gid < MLPC) {
        int o = gid;
        float s = g[o] / sqrtf(rv[o] + EPSF);
        bs_g[o] = s * bcv[o];
        sC4_g[o] = make_float4(s * W[o * CIN + 64],
                               s * W[o * CIN + 65],
                               s * W[o * CIN + 66],
                               bt[o] - s * rm[o]);
    }
}

// ---------------------------------------------------------------------------
// K1: Th = X @ Wt, register-tiled GEMM, fp16 output (unchanged, R12-proven)
// ---------------------------------------------------------------------------
__global__ __launch_bounds__(128) void k_pre(
    const float* __restrict__ xyz, const float* __restrict__ pts)
{
    __shared__ float Wsh[CIN * MLPC];
    __shared__ float Xs[CIN * 64];

    int tid = threadIdx.x;

    {
        const float4* src = (const float4*)Wt_g;
        float4* dst = (float4*)Wsh;
        for (int i = tid; i < CIN * MLPC / 4; i += 128) dst[i] = src[i];
    }

    int b  = blockIdx.x >> 6;
    int m0 = (blockIdx.x & 63) << 6;

    for (int i = tid; i < CIN * 16; i += 128) {
        int c = i >> 4, j = (i & 15) << 2;
        const float* src = (c < DD) ? &pts[((b << 6) + c) * NN + m0 + j]
                                    : &xyz[(b * 3 + (c - DD)) * NN + m0 + j];
        *(float4*)&Xs[c * 64 + j] = *(const float4*)src;
    }
    __syncthreads();

    if (tid < 64) {
        float x = Xs[64 * 64 + tid], y = Xs[65 * 64 + tid], z = Xs[66 * 64 + tid];
        P4_g[b * NN + m0 + tid] = make_float4(x, y, z, fmaf(z, z, fmaf(y, y, x * x)));
    }

    int om = tid & 7;
    int pm = tid >> 3;

    unsigned long long acc[4][4];
#pragma unroll
    for (int p = 0; p < 4; p++)
#pragma unroll
        for (int q = 0; q < 4; q++) acc[p][q] = 0ull;

    const float* wp = &Wsh[om * 8];
    const float* xp = &Xs[pm * 4];

#pragma unroll 2
    for (int c = 0; c < CIN; c++) {
        ulonglong2 wa = *(const ulonglong2*)(wp + c * MLPC);
        ulonglong2 wb = *(const ulonglong2*)(wp + c * MLPC + 4);
        float4 xv = *(const float4*)(xp + c * 64);
        unsigned long long wv[4] = { wa.x, wa.y, wb.x, wb.y };
        float xs[4] = { xv.x, xv.y, xv.z, xv.w };
#pragma unroll
        for (int p = 0; p < 4; p++) {
            unsigned long long xx = pack2(xs[p], xs[p]);
#pragma unroll
            for (int q = 0; q < 4; q++) ffma2(acc[p][q], wv[q], xx);
        }
    }

    float4 bsA = __ldg((const float4*)&bs_g[om * 8]);
    float4 bsB = __ldg((const float4*)&bs_g[om * 8 + 4]);
    float bsv[8] = { bsA.x, bsA.y, bsA.z, bsA.w, bsB.x, bsB.y, bsB.z, bsB.w };

#pragma unroll
    for (int p = 0; p < 4; p++) {
        int gm = b * NN + m0 + pm * 4 + p;
        union { __half2 h2[4]; uint4 u4; } cvt;
#pragma unroll
        for (int q = 0; q < 4; q++) {
            float lo, hi;
            unpack2(acc[p][q], lo, hi);
            cvt.h2[q] = __floats2half2_rn(lo + bsv[2 * q], hi + bsv[2 * q + 1]);
        }
        *((uint4*)Th_g + (size_t)gm * 8 + om) = cvt.u4;
    }
}

// ---------------------------------------------------------------------------
// K2: warp-autonomous ball query + fp16 gather-max (unchanged, R8-proven)
// ---------------------------------------------------------------------------
__global__ __launch_bounds__(256) void k_ball()
{
    __shared__ int gi_sh[8][KK];

    int tid  = threadIdx.x;
    int w    = tid >> 5;
    int lane = tid & 31;
    unsigned below = (1u << lane) - 1u;

    int b  = blockIdx.x >> 9;
    int n  = ((blockIdx.x & 511) << 3) + w;
    int bN = b * NN;

    float4 q = P4_g[bN + n];

    int cnt = 0;
#pragma unroll 1
    for (int base = 0; base < NN; base += 64) {
        float4 c0 = __ldg(&P4_g[bN + base + lane]);
        float4 c1 = __ldg(&P4_g[bN + base + 32 + lane]);

        float d0 = q.w + c0.w - 2.0f * fmaf(q.z, c0.z, fmaf(q.y, c0.y, q.x * c0.x));
        float d1 = q.w + c1.w - 2.0f * fmaf(q.z, c1.z, fmaf(q.y, c1.y, q.x * c1.x));

        unsigned m0 = __ballot_sync(0xffffffffu, d0 <= R2);
        unsigned m1 = __ballot_sync(0xffffffffu, d1 <= R2);

        if (d0 <= R2) {
            int pos = cnt + __popc(m0 & below);
            if (pos < KK) gi_sh[w][pos] = base + lane;
        }
        int n0 = __popc(m0);
        if (d1 <= R2) {
            int pos = cnt + n0 + __popc(m1 & below);
            if (pos < KK) gi_sh[w][pos] = base + 32 + lane;
        }
        cnt += n0 + __popc(m1);
        if (cnt >= KK) break;
    }
    __syncwarp();

    int cap   = (cnt < KK) ? cnt : KK;
    int gidx0 = gi_sh[w][0];

    __half2 mx = __float2half2_rn(-65504.0f);
#pragma unroll
    for (int j = 0; j < KK; j++) {
        int gj = (j < cap) ? gi_sh[w][j] : gidx0;
        const __half2* tr = ((const __half2*)Th_g) + (((size_t)(bN + gj)) << 5) + lane;
        mx = __hmax2(mx, __ldg(tr));
    }
    float2 m = __half22float2(mx);

    float4 a0 = sC4_g[2 * lane];
    float4 a1 = sC4_g[2 * lane + 1];
    float u0 = a0.w - fmaf(a0.z, q.z, fmaf(a0.y, q.y, a0.x * q.x));
    float u1 = a1.w - fmaf(a1.z, q.z, fmaf(a1.y, q.y, a1.x * q.x));

    float2 outv = make_float2(fmaxf(m.x + u0, 0.0f), fmaxf(m.y + u1, 0.0f));
    *(float2*)&np_g[((size_t)(bN + n)) * MLPC + 2 * lane] = outv;
}

// ---------------------------------------------------------------------------
// K3: resnet 64->128->64 + residual ReLU via mma.sync m16n8k16 fp16 HMMA.
// 256 thr / 128 points per CTA, grid 256.
// Phase 1: D1[128pt x 128o]  = V . W1^T   (warp: 32pt x 64o, 4 k-steps)
// Phase 2: D2[128pt x 64o2]  = X1 . W2^T  (warp: 32pt x 32o2, 8 k-steps)
// smem (halves): Vh[128][72] @0, W1h[128][72] @9216, X1h[128][136] @0 (reuse),
//                W2h[64][136] @18432.  Total 27136 halves = 54272 B.
// ---------------------------------------------------------------------------
__global__ __launch_bounds__(256) void k_resnet_mma(
    const float* __restrict__ pts, float* __restrict__ out)
{
    extern __shared__ __align__(16) __half hsm[];
    __half* Vh  = hsm;            // [128][72]
    __half* W1h = hsm + 9216;     // [128][72]
    __half* X1h = hsm;            // [128][136] (overlaps Vh+W1h)
    __half* W2h = hsm + 18432;    // [64][136]
    __shared__ float t1sh[P1C];
    __shared__ float t2sh[P2C];

    int tid = threadIdx.x, wid = tid >> 5, lane = tid & 31;
    int m0 = blockIdx.x << 7;
    int b  = m0 >> 12;
    int n0 = m0 & (NN - 1);

    if (tid < P1C) t1sh[tid] = t1_g[tid];
    if (tid < P2C) t2sh[tid] = t2_g[tid];

    // stage weights (padded rows, 16B chunks)
    for (int i = tid; i < 1024; i += 256) {
        int r = i >> 3, c = i & 7;
        *(uint4*)(W1h + r * 72 + c * 8) = *(const uint4*)(W1f16_g + r * 64 + c * 8);
    }
    for (int i = tid; i < 1024; i += 256) {
        int r = i >> 4, c = i & 15;
        *(uint4*)(W2h + r * 136 + c * 8) = *(const uint4*)(W2f16_g + r * 128 + c * 8);
    }
    // V -> fp16 rows
    for (int i = tid; i < 1024; i += 256) {
        int r = i >> 3, c = i & 7;
        const float4* src = (const float4*)(np_g + (size_t)(m0 + r) * MLPC + c * 8);
        float4 x = src[0], y = src[1];
        union { __half2 h2[4]; uint4 u4; } cv;
        cv.h2[0] = __floats2half2_rn(x.x, x.y);
        cv.h2[1] = __floats2half2_rn(x.z, x.w);
        cv.h2[2] = __floats2half2_rn(y.x, y.y);
        cv.h2[3] = __floats2half2_rn(y.z, y.w);
        *(uint4*)(Vh + r * 72 + c * 8) = cv.u4;
    }
    __syncthreads();

    uint32_t Vu  = smem_u32(Vh);
    uint32_t W1u = smem_u32(W1h);
    uint32_t X1u = smem_u32(X1h);
    uint32_t W2u = smem_u32(W2h);

    int lr = lane & 7, lm = lane >> 3;
    int arow8 = (lm & 1) * 8, acol8 = (lm >> 1) * 8;  // A frag: m0k0,m8k0,m0k8,m8k8
    int brow8 = (lm >> 1) * 8, bcol8 = (lm & 1) * 8;  // B pair: n0k0,n0k8,n8k0,n8k8

    int pt0 = (wid & 3) * 32;
    int o0  = (wid >> 2) * 64;

    // ---- Phase 1 ----
    float acc[2][8][4];
#pragma unroll
    for (int m = 0; m < 2; m++)
#pragma unroll
        for (int n = 0; n < 8; n++)
#pragma unroll
            for (int q = 0; q < 4; q++) acc[m][n][q] = 0.0f;

#pragma unroll
    for (int ks = 0; ks < 4; ks++) {
        int k0 = ks * 16;
        uint32_t af[2][4];
#pragma unroll
        for (int m = 0; m < 2; m++) {
            uint32_t a = Vu + (uint32_t)(((pt0 + m * 16 + lr + arow8) * 72
                                          + k0 + acol8) * 2);
            ldsm_x4(af[m][0], af[m][1], af[m][2], af[m][3], a);
        }
        uint32_t bf[8][2];
#pragma unroll
        for (int nb = 0; nb < 4; nb++) {
            uint32_t a = W1u + (uint32_t)(((o0 + nb * 16 + lr + brow8) * 72
                                           + k0 + bcol8) * 2);
            uint32_t r0, r1, r2, r3;
            ldsm_x4(r0, r1, r2, r3, a);
            bf[2 * nb][0] = r0; bf[2 * nb][1] = r1;
            bf[2 * nb + 1][0] = r2; bf[2 * nb + 1][1] = r3;
        }
#pragma unroll
        for (int m = 0; m < 2; m++)
#pragma unroll
            for (int n = 0; n < 8; n++)
                mma16816(acc[m][n], af[m], bf[n]);
    }
    __syncthreads();   // phase-1 smem reads complete before X1 overwrite

    // ---- Epilogue 1: X1 = relu(D1 + t1), fp16, [pt][o] stride 136 ----
    int drow = lane >> 2, dcol = (lane & 3) * 2;
#pragma unroll
    for (int m = 0; m < 2; m++)
#pragma unroll
        for (int n = 0; n < 8; n++) {
            int pt  = pt0 + m * 16 + drow;
            int col = o0 + n * 8 + dcol;
            float ta = t1sh[col], tb = t1sh[col + 1];
            __half2 h0 = __floats2half2_rn(fmaxf(acc[m][n][0] + ta, 0.0f),
                                           fmaxf(acc[m][n][1] + tb, 0.0f));
            __half2 h1 = __floats2half2_rn(fmaxf(acc[m][n][2] + ta, 0.0f),
                                           fmaxf(acc[m][n][3] + tb, 0.0f));
            *(uint32_t*)(X1h + pt * 136 + col)       = *(uint32_t*)&h0;
            *(uint32_t*)(X1h + (pt + 8) * 136 + col) = *(uint32_t*)&h1;
        }
    __syncthreads();

    // ---- Phase 2 ----
    int o20 = (wid >> 2) * 32;
    float acc2[2][4][4];
#pragma unroll
    for (int m = 0; m < 2; m++)
#pragma unroll
        for (int n = 0; n < 4; n++)
#pragma unroll
            for (int q = 0; q < 4; q++) acc2[m][n][q] = 0.0f;

#pragma unroll
    for (int ks = 0; ks < 8; ks++) {
        int k0 = ks * 16;
        uint32_t af[2][4];
#pragma unroll
        for (int m = 0; m < 2; m++) {
            uint32_t a = X1u + (uint32_t)(((pt0 + m * 16 + lr + arow8) * 136
                                           + k0 + acol8) * 2);
            ldsm_x4(af[m][0], af[m][1], af[m][2], af[m][3], a);
        }
        uint32_t bf[4][2];
#pragma unroll
        for (int nb = 0; nb < 2; nb++) {
            uint32_t a = W2u + (uint32_t)(((o20 + nb * 16 + lr + brow8) * 136
                                           + k0 + bcol8) * 2);
            uint32_t r0, r1, r2, r3;
            ldsm_x4(r0, r1, r2, r3, a);
            bf[2 * nb][0] = r0; bf[2 * nb][1] = r1;
            bf[2 * nb + 1][0] = r2; bf[2 * nb + 1][1] = r3;
        }
#pragma unroll
        for (int m = 0; m < 2; m++)
#pragma unroll
            for (int n = 0; n < 4; n++)
                mma16816(acc2[m][n], af[m], bf[n]);
    }

    // ---- Epilogue 2: out = relu(D2 + t2 + pts) ----
#pragma unroll
    for (int m = 0; m < 2; m++)
#pragma unroll
        for (int n = 0; n < 4; n++) {
            int ptA = pt0 + m * 16 + drow;
            int ptB = ptA + 8;
            int o2  = o20 + n * 8 + dcol;
            float ta = t2sh[o2], tb = t2sh[o2 + 1];
            size_t g0 = ((size_t)(b * P2C + o2)) * NN + n0;
            size_t g1 = ((size_t)(b * P2C + o2 + 1)) * NN + n0;
            out[g0 + ptA] = fmaxf(acc2[m][n][0] + ta + __ldg(&pts[g0 + ptA]), 0.0f);
            out[g1 + ptA] = fmaxf(acc2[m][n][1] + tb + __ldg(&pts[g1 + ptA]), 0.0f);
            out[g0 + ptB] = fmaxf(acc2[m][n][2] + ta + __ldg(&pts[g0 + ptB]), 0.0f);
            out[g1 + ptB] = fmaxf(acc2[m][n][3] + tb + __ldg(&pts[g1 + ptB]), 0.0f);
        }
}

// ---------------------------------------------------------------------------
// Launch
// ---------------------------------------------------------------------------
extern "C" void kernel_launch(void* const* d_in, const int* in_sizes, int n_in,
                              void* d_out, int out_size)
{
    (void)n_in; (void)out_size;

    const float* xyz = (const float*)d_in[0];
    const float* pts = (const float*)d_in[1];
    const float* W   = (const float*)d_in[2];
    const float* bcv = (const float*)d_in[3];
    const float* g   = (const float*)d_in[4];
    const float* bt  = (const float*)d_in[5];
    const float* rm  = (const float*)d_in[6];
    const float* rv  = (const float*)d_in[7];
    const float* W1  = (const float*)d_in[8];
    const float* b1  = (const float*)d_in[9];
    const float* g1  = (const float*)d_in[10];
    const float* bt1 = (const float*)d_in[11];
    const float* rm1 = (const float*)d_in[12];
    const float* rv1 = (const float*)d_in[13];
    const float* W2  = (const float*)d_in[14];
    const float* b2  = (const float*)d_in[15];
    const float* g2  = (const float*)d_in[16];
    const float* bt2 = (const float*)d_in[17];
    const float* rm2 = (const float*)d_in[18];
    const float* rv2 = (const float*)d_in[19];

    float* out = (float*)d_out;

    static const size_t smem3 = 27136 * sizeof(__half);   // 54272 B
    cudaFuncSetAttribute(k_resnet_mma, cudaFuncAttributeMaxDynamicSharedMemorySize,
                         (int)smem3);

    cudaMemcpyAsync(out, xyz, (size_t)in_sizes[0] * sizeof(float),
                    cudaMemcpyDeviceToDevice, 0);

    k_wprep<<<32, 256>>>(W, bcv, g, bt, rm, rv,
                         W1, b1, g1, bt1, rm1, rv1,
                         W2, b2, g2, bt2, rm2, rv2);
    k_pre<<<(BB * NN) / 64, 128>>>(xyz, pts);
    k_ball<<<(BB * NN) / 8, 256>>>();
    k_resnet_mma<<<(BB * NN) / 128, 256, smem3>>>(pts, out + in_sizes[0]);
}

// round 16
// speedup vs baseline: 1.4081x; 1.0350x over previous
#include <cuda_runtime.h>
#include <cuda_fp16.h>
#include <cstdint>
#include <cstddef>

#define BB   8
#define NN   4096
#define KK   32
#define DD   64
#define CIN  67
#define MLPC 64
#define P1C  128
#define P2C  64
#define R2   0.04f
#define EPSF 1e-5f

// Scratch (device globals; no allocation allowed)
__device__ __half  Th_g[BB * NN * MLPC];   // fp16 s*(pts·Wd + xyz·Wx + b), 128B rows
__device__ float4  P4_g[BB * NN];          // (x, y, z, ||p||^2)
__device__ float   np_g[BB * NN * MLPC];   // max-pooled features, n-major rows
__device__ float4  sC4_g[MLPC];            // {s*Wx0, s*Wx1, s*Wx2, bt - s*rm}
__device__ float   bs_g[MLPC];             // s*b
__device__ float   t1_g[P1C];              // s1*(b1-rm1)+bt1
__device__ float   t2_g[P2C];              // s2*(b2-rm2)+bt2
__device__ __half  W1f16_g[P1C * P2C];     // s1-folded W1, fp16, [o:128][k:64]
__device__ __half  W2f16_g[P2C * P1C];     // s2-folded W2, fp16, [o2:64][k:128]
__device__ __half  W0f16_g[MLPC * 80];     // s-folded W, fp16, [o:64][k:80 zero-pad]

// ---- mma.sync helpers -----------------------------------------------------
__device__ __forceinline__ uint32_t smem_u32(const void* p) {
    uint32_t a;
    asm("{ .reg .u64 t; cvta.to.shared.u64 t, %1; cvt.u32.u64 %0, t; }"
        : "=r"(a) : "l"(p));
    return a;
}
__device__ __forceinline__ void ldsm_x4(uint32_t& r0, uint32_t& r1,
                                        uint32_t& r2, uint32_t& r3, uint32_t addr) {
    asm volatile("ldmatrix.sync.aligned.m8n8.x4.shared.b16 {%0,%1,%2,%3}, [%4];"
                 : "=r"(r0), "=r"(r1), "=r"(r2), "=r"(r3) : "r"(addr));
}
__device__ __forceinline__ void mma16816(float* c, const uint32_t* a,
                                         const uint32_t* b) {
    asm volatile(
        "mma.sync.aligned.m16n8k16.row.col.f32.f16.f16.f32 "
        "{%0,%1,%2,%3}, {%4,%5,%6,%7}, {%8,%9}, {%0,%1,%2,%3};"
        : "+f"(c[0]), "+f"(c[1]), "+f"(c[2]), "+f"(c[3])
        : "r"(a[0]), "r"(a[1]), "r"(a[2]), "r"(a[3]), "r"(b[0]), "r"(b[1]));
}

// ---------------------------------------------------------------------------
// K0: one-time weight prep (folded; fp16 images for mma paths)
// ---------------------------------------------------------------------------
__global__ __launch_bounds__(256) void k_wprep(
    const float* __restrict__ W,   const float* __restrict__ bcv,
    const float* __restrict__ g,   const float* __restrict__ bt,
    const float* __restrict__ rm,  const float* __restrict__ rv,
    const float* __restrict__ W1,  const float* __restrict__ b1,
    const float* __restrict__ g1,  const float* __restrict__ bt1,
    const float* __restrict__ rm1, const float* __restrict__ rv1,
    const float* __restrict__ W2,  const float* __restrict__ b2,
    const float* __restrict__ g2,  const float* __restrict__ bt2,
    const float* __restrict__ rm2, const float* __restrict__ rv2)
{
    int gid = blockIdx.x * 256 + threadIdx.x;

    if (gid < MLPC * 80) {                 // W0 fp16: [o:64][k:80], zero-pad k>=67
        int o = gid / 80, k = gid - o * 80;
        float s = g[o] / sqrtf(rv[o] + EPSF);
        W0f16_g[gid] = __float2half((k < CIN) ? s * W[o * CIN + k] : 0.0f);
    }
    if (gid < P1C * P2C) {                 // W1 fp16: [o:128][k:64]
        int o = gid >> 6, k = gid & 63;
        float s1 = g1[o] / sqrtf(rv1[o] + EPSF);
        W1f16_g[gid] = __float2half(s1 * W1[o * P2C + k]);
    }
    if (gid < P2C * P1C) {                 // W2 fp16: [o2:64][k:128]
        int o2 = gid >> 7, k = gid & 127;
        float s2 = g2[o2] / sqrtf(rv2[o2] + EPSF);
        W2f16_g[gid] = __float2half(s2 * W2[o2 * P1C + k]);
    }
    if (gid < P1C) {
        float s1 = g1[gid] / sqrtf(rv1[gid] + EPSF);
        t1_g[gid] = fmaf(s1, b1[gid] - rm1[gid], bt1[gid]);
    }
    if (gid < P2C) {
        float s2 = g2[gid] / sqrtf(rv2[gid] + EPSF);
        t2_g[gid] = fmaf(s2, b2[gid] - rm2[gid], bt2[gid]);
    }
    if (gid < MLPC) {
        int o = gid;
        float s = g[o] / sqrtf(rv[o] + EPSF);
        bs_g[o] = s * bcv[o];
        sC4_g[o] = make_float4(s * W[o * CIN + 64],
                               s * W[o * CIN + 65],
                               s * W[o * CIN + 66],
                               bt[o] - s * rm[o]);
    }
}

// ---------------------------------------------------------------------------
// K1: Th = X @ W0^T via mma.sync HMMA. 256 thr / 128 pts, grid 256.
// A = X fp16 [pt:128][k:88pad], B = W0 fp16 [o:64][k:88pad]. 5 k-steps (K=80).
// Warp tile: 16 pt x 64 o. P4 computed from fp32 globals (exact).
// ---------------------------------------------------------------------------
__global__ __launch_bounds__(256) void k_pre_mma(
    const float* __restrict__ xyz, const float* __restrict__ pts)
{
    __shared__ __align__(16) __half Xh[128 * 88];   // 22528 B
    __shared__ __align__(16) __half Wh[64 * 88];    // 11264 B

    int tid = threadIdx.x, wid = tid >> 5, lane = tid & 31;
    int b  = blockIdx.x >> 5;              // 32 blocks per batch
    int m0 = (blockIdx.x & 31) << 7;       // 128 pts per block

    // zero Xh (covers k-pad columns)
    for (int i = tid; i < 128 * 88 / 8; i += 256)
        ((uint4*)Xh)[i] = make_uint4(0, 0, 0, 0);

    // W0 copy: [o][80] image -> [o][88] smem rows
    for (int i = tid; i < 64 * 10; i += 256) {
        int r = i / 10, c = i - r * 10;
        *(uint4*)(Wh + r * 88 + c * 8) = *(const uint4*)(W0f16_g + r * 80 + c * 8);
    }
    __syncthreads();

    // X: coalesced channel-major loads, fp16 transposed stores [pt][c]
    for (int i = tid; i < CIN * 32; i += 256) {
        int c = i >> 5, j = (i & 31) << 2;
        const float* src = (c < DD) ? &pts[((b << 6) + c) * NN + m0 + j]
                                    : &xyz[(b * 3 + (c - DD)) * NN + m0 + j];
        float4 v = *(const float4*)src;
        Xh[(j + 0) * 88 + c] = __float2half(v.x);
        Xh[(j + 1) * 88 + c] = __float2half(v.y);
        Xh[(j + 2) * 88 + c] = __float2half(v.z);
        Xh[(j + 3) * 88 + c] = __float2half(v.w);
    }

    // P4 from fp32 globals (exact ball-query inputs)
    if (tid < 128) {
        int m = m0 + tid;
        float x = xyz[(b * 3 + 0) * NN + m];
        float y = xyz[(b * 3 + 1) * NN + m];
        float z = xyz[(b * 3 + 2) * NN + m];
        P4_g[b * NN + m] = make_float4(x, y, z, fmaf(z, z, fmaf(y, y, x * x)));
    }
    __syncthreads();

    uint32_t Xu = smem_u32(Xh);
    uint32_t Wu = smem_u32(Wh);

    int lr = lane & 7, lm = lane >> 3;
    int arow8 = (lm & 1) * 8, acol8 = (lm >> 1) * 8;
    int brow8 = (lm >> 1) * 8, bcol8 = (lm & 1) * 8;

    int pt0 = wid * 16;

    float acc[8][4];
#pragma unroll
    for (int n = 0; n < 8; n++)
#pragma unroll
        for (int q = 0; q < 4; q++) acc[n][q] = 0.0f;

#pragma unroll
    for (int ks = 0; ks < 5; ks++) {
        int k0 = ks * 16;
        uint32_t af[4];
        {
            uint32_t a = Xu + (uint32_t)(((pt0 + lr + arow8) * 88 + k0 + acol8) * 2);
            ldsm_x4(af[0], af[1], af[2], af[3], a);
        }
        uint32_t bf[8][2];
#pragma unroll
        for (int nb = 0; nb < 4; nb++) {
            uint32_t a = Wu + (uint32_t)(((nb * 16 + lr + brow8) * 88 + k0 + bcol8) * 2);
            uint32_t r0, r1, r2, r3;
            ldsm_x4(r0, r1, r2, r3, a);
            bf[2 * nb][0] = r0; bf[2 * nb][1] = r1;
            bf[2 * nb + 1][0] = r2; bf[2 * nb + 1][1] = r3;
        }
#pragma unroll
        for (int n = 0; n < 8; n++)
            mma16816(acc[n], af, bf[n]);
    }

    // Epilogue: Th[pt][o] = fp16(acc + bs[o])
    int drow = lane >> 2, dcol = (lane & 3) * 2;
#pragma unroll
    for (int n = 0; n < 8; n++) {
        int col = n * 8 + dcol;
        float ba = __ldg(&bs_g[col]);
        float bbv = __ldg(&bs_g[col + 1]);
        int gmA = b * NN + m0 + pt0 + drow;
        int gmB = gmA + 8;
        __half2 h0 = __floats2half2_rn(acc[n][0] + ba, acc[n][1] + bbv);
        __half2 h1 = __floats2half2_rn(acc[n][2] + ba, acc[n][3] + bbv);
        ((uint32_t*)Th_g)[(size_t)gmA * 32 + (col >> 1)] = *(uint32_t*)&h0;
        ((uint32_t*)Th_g)[(size_t)gmB * 32 + (col >> 1)] = *(uint32_t*)&h1;
    }
}

// ---------------------------------------------------------------------------
// K2: warp-autonomous ball query + fp16 gather-max (unchanged, R8-proven)
// ---------------------------------------------------------------------------
__global__ __launch_bounds__(256) void k_ball()
{
    __shared__ int gi_sh[8][KK];

    int tid  = threadIdx.x;
    int w    = tid >> 5;
    int lane = tid & 31;
    unsigned below = (1u << lane) - 1u;

    int b  = blockIdx.x >> 9;
    int n  = ((blockIdx.x & 511) << 3) + w;
    int bN = b * NN;

    float4 q = P4_g[bN + n];

    int cnt = 0;
#pragma unroll 1
    for (int base = 0; base < NN; base += 64) {
        float4 c0 = __ldg(&P4_g[bN + base + lane]);
        float4 c1 = __ldg(&P4_g[bN + base + 32 + lane]);

        float d0 = q.w + c0.w - 2.0f * fmaf(q.z, c0.z, fmaf(q.y, c0.y, q.x * c0.x));
        float d1 = q.w + c1.w - 2.0f * fmaf(q.z, c1.z, fmaf(q.y, c1.y, q.x * c1.x));

        unsigned m0 = __ballot_sync(0xffffffffu, d0 <= R2);
        unsigned m1 = __ballot_sync(0xffffffffu, d1 <= R2);

        if (d0 <= R2) {
            int pos = cnt + __popc(m0 & below);
            if (pos < KK) gi_sh[w][pos] = base + lane;
        }
        int n0 = __popc(m0);
        if (d1 <= R2) {
            int pos = cnt + n0 + __popc(m1 & below);
            if (pos < KK) gi_sh[w][pos] = base + 32 + lane;
        }
        cnt += n0 + __popc(m1);
        if (cnt >= KK) break;
    }
    __syncwarp();

    int cap   = (cnt < KK) ? cnt : KK;
    int gidx0 = gi_sh[w][0];

    __half2 mx = __float2half2_rn(-65504.0f);
#pragma unroll
    for (int j = 0; j < KK; j++) {
        int gj = (j < cap) ? gi_sh[w][j] : gidx0;
        const __half2* tr = ((const __half2*)Th_g) + (((size_t)(bN + gj)) << 5) + lane;
        mx = __hmax2(mx, __ldg(tr));
    }
    float2 m = __half22float2(mx);

    float4 a0 = sC4_g[2 * lane];
    float4 a1 = sC4_g[2 * lane + 1];
    float u0 = a0.w - fmaf(a0.z, q.z, fmaf(a0.y, q.y, a0.x * q.x));
    float u1 = a1.w - fmaf(a1.z, q.z, fmaf(a1.y, q.y, a1.x * q.x));

    float2 outv = make_float2(fmaxf(m.x + u0, 0.0f), fmaxf(m.y + u1, 0.0f));
    *(float2*)&np_g[((size_t)(bN + n)) * MLPC + 2 * lane] = outv;
}

// ---------------------------------------------------------------------------
// K3: resnet via mma.sync HMMA (unchanged, R15-proven 16.2us)
// ---------------------------------------------------------------------------
__global__ __launch_bounds__(256) void k_resnet_mma(
    const float* __restrict__ pts, float* __restrict__ out)
{
    extern __shared__ __align__(16) __half hsm[];
    __half* Vh  = hsm;            // [128][72]
    __half* W1h = hsm + 9216;     // [128][72]
    __half* X1h = hsm;            // [128][136] (overlaps Vh+W1h)
    __half* W2h = hsm + 18432;    // [64][136]
    __shared__ float t1sh[P1C];
    __shared__ float t2sh[P2C];

    int tid = threadIdx.x, wid = tid >> 5, lane = tid & 31;
    int m0 = blockIdx.x << 7;
    int b  = m0 >> 12;
    int n0 = m0 & (NN - 1);

    if (tid < P1C) t1sh[tid] = t1_g[tid];
    if (tid < P2C) t2sh[tid] = t2_g[tid];

    for (int i = tid; i < 1024; i += 256) {
        int r = i >> 3, c = i & 7;
        *(uint4*)(W1h + r * 72 + c * 8) = *(const uint4*)(W1f16_g + r * 64 + c * 8);
    }
    for (int i = tid; i < 1024; i += 256) {
        int r = i >> 4, c = i & 15;
        *(uint4*)(W2h + r * 136 + c * 8) = *(const uint4*)(W2f16_g + r * 128 + c * 8);
    }
    for (int i = tid; i < 1024; i += 256) {
        int r = i >> 3, c = i & 7;
        const float4* src = (const float4*)(np_g + (size_t)(m0 + r) * MLPC + c * 8);
        float4 x = src[0], y = src[1];
        union { __half2 h2[4]; uint4 u4; } cv;
        cv.h2[0] = __floats2half2_rn(x.x, x.y);
        cv.h2[1] = __floats2half2_rn(x.z, x.w);
        cv.h2[2] = __floats2half2_rn(y.x, y.y);
        cv.h2[3] = __floats2half2_rn(y.z, y.w);
        *(uint4*)(Vh + r * 72 + c * 8) = cv.u4;
    }
    __syncthreads();

    uint32_t Vu  = smem_u32(Vh);
    uint32_t W1u = smem_u32(W1h);
    uint32_t X1u = smem_u32(X1h);
    uint32_t W2u = smem_u32(W2h);

    int lr = lane & 7, lm = lane >> 3;
    int arow8 = (lm & 1) * 8, acol8 = (lm >> 1) * 8;
    int brow8 = (lm >> 1) * 8, bcol8 = (lm & 1) * 8;

    int pt0 = (wid & 3) * 32;
    int o0  = (wid >> 2) * 64;

    float acc[2][8][4];
#pragma unroll
    for (int m = 0; m < 2; m++)
#pragma unroll
        for (int n = 0; n < 8; n++)
#pragma unroll
            for (int q = 0; q < 4; q++) acc[m][n][q] = 0.0f;

#pragma unroll
    for (int ks = 0; ks < 4; ks++) {
        int k0 = ks * 16;
        uint32_t af[2][4];
#pragma unroll
        for (int m = 0; m < 2; m++) {
            uint32_t a = Vu + (uint32_t)(((pt0 + m * 16 + lr + arow8) * 72
                                          + k0 + acol8) * 2);
            ldsm_x4(af[m][0], af[m][1], af[m][2], af[m][3], a);
        }
        uint32_t bf[8][2];
#pragma unroll
        for (int nb = 0; nb < 4; nb++) {
            uint32_t a = W1u + (uint32_t)(((o0 + nb * 16 + lr + brow8) * 72
                                           + k0 + bcol8) * 2);
            uint32_t r0, r1, r2, r3;
            ldsm_x4(r0, r1, r2, r3, a);
            bf[2 * nb][0] = r0; bf[2 * nb][1] = r1;
            bf[2 * nb + 1][0] = r2; bf[2 * nb + 1][1] = r3;
        }
#pragma unroll
        for (int m = 0; m < 2; m++)
#pragma unroll
            for (int n = 0; n < 8; n++)
                mma16816(acc[m][n], af[m], bf[n]);
    }
    __syncthreads();

    int drow = lane >> 2, dcol = (lane & 3) * 2;
#pragma unroll
    for (int m = 0; m < 2; m++)
#pragma unroll
        for (int n = 0; n < 8; n++) {
            int pt  = pt0 + m * 16 + drow;
            int col = o0 + n * 8 + dcol;
            float ta = t1sh[col], tb = t1sh[col + 1];
            __half2 h0 = __floats2half2_rn(fmaxf(acc[m][n][0] + ta, 0.0f),
                                           fmaxf(acc[m][n][1] + tb, 0.0f));
            __half2 h1 = __floats2half2_rn(fmaxf(acc[m][n][2] + ta, 0.0f),
                                           fmaxf(acc[m][n][3] + tb, 0.0f));
            *(uint32_t*)(X1h + pt * 136 + col)       = *(uint32_t*)&h0;
            *(uint32_t*)(X1h + (pt + 8) * 136 + col) = *(uint32_t*)&h1;
        }
    __syncthreads();

    int o20 = (wid >> 2) * 32;
    float acc2[2][4][4];
#pragma unroll
    for (int m = 0; m < 2; m++)
#pragma unroll
        for (int n = 0; n < 4; n++)
#pragma unroll
            for (int q = 0; q < 4; q++) acc2[m][n][q] = 0.0f;

#pragma unroll
    for (int ks = 0; ks < 8; ks++) {
        int k0 = ks * 16;
        uint32_t af[2][4];
#pragma unroll
        for (int m = 0; m < 2; m++) {
            uint32_t a = X1u + (uint32_t)(((pt0 + m * 16 + lr + arow8) * 136
                                           + k0 + acol8) * 2);
            ldsm_x4(af[m][0], af[m][1], af[m][2], af[m][3], a);
        }
        uint32_t bf[4][2];
#pragma unroll
        for (int nb = 0; nb < 2; nb++) {
            uint32_t a = W2u + (uint32_t)(((o20 + nb * 16 + lr + brow8) * 136
                                           + k0 + bcol8) * 2);
            uint32_t r0, r1, r2, r3;
            ldsm_x4(r0, r1, r2, r3, a);
            bf[2 * nb][0] = r0; bf[2 * nb][1] = r1;
            bf[2 * nb + 1][0] = r2; bf[2 * nb + 1][1] = r3;
        }
#pragma unroll
        for (int m = 0; m < 2; m++)
#pragma unroll
            for (int n = 0; n < 4; n++)
                mma16816(acc2[m][n], af[m], bf[n]);
    }

#pragma unroll
    for (int m = 0; m < 2; m++)
#pragma unroll
        for (int n = 0; n < 4; n++) {
            int ptA = pt0 + m * 16 + drow;
            int ptB = ptA + 8;
            int o2  = o20 + n * 8 + dcol;
            float ta = t2sh[o2], tb = t2sh[o2 + 1];
            size_t g0 = ((size_t)(b * P2C + o2)) * NN + n0;
            size_t g1 = ((size_t)(b * P2C + o2 + 1)) * NN + n0;
            out[g0 + ptA] = fmaxf(acc2[m][n][0] + ta + __ldg(&pts[g0 + ptA]), 0.0f);
            out[g1 + ptA] = fmaxf(acc2[m][n][1] + tb + __ldg(&pts[g1 + ptA]), 0.0f);
            out[g0 + ptB] = fmaxf(acc2[m][n][2] + ta + __ldg(&pts[g0 + ptB]), 0.0f);
            out[g1 + ptB] = fmaxf(acc2[m][n][3] + tb + __ldg(&pts[g1 + ptB]), 0.0f);
        }
}

// ---------------------------------------------------------------------------
// Launch
// ---------------------------------------------------------------------------
extern "C" void kernel_launch(void* const* d_in, const int* in_sizes, int n_in,
                              void* d_out, int out_size)
{
    (void)n_in; (void)out_size;

    const float* xyz = (const float*)d_in[0];
    const float* pts = (const float*)d_in[1];
    const float* W   = (const float*)d_in[2];
    const float* bcv = (const float*)d_in[3];
    const float* g   = (const float*)d_in[4];
    const float* bt  = (const float*)d_in[5];
    const float* rm  = (const float*)d_in[6];
    const float* rv  = (const float*)d_in[7];
    const float* W1  = (const float*)d_in[8];
    const float* b1  = (const float*)d_in[9];
    const float* g1  = (const float*)d_in[10];
    const float* bt1 = (const float*)d_in[11];
    const float* rm1 = (const float*)d_in[12];
    const float* rv1 = (const float*)d_in[13];
    const float* W2  = (const float*)d_in[14];
    const float* b2  = (const float*)d_in[15];
    const float* g2  = (const float*)d_in[16];
    const float* bt2 = (const float*)d_in[17];
    const float* rm2 = (const float*)d_in[18];
    const float* rv2 = (const float*)d_in[19];

    float* out = (float*)d_out;

    static const size_t smem3 = 27136 * sizeof(__half);   // 54272 B
    cudaFuncSetAttribute(k_resnet_mma, cudaFuncAttributeMaxDynamicSharedMemorySize,
                         (int)smem3);

    cudaMemcpyAsync(out, xyz, (size_t)in_sizes[0] * sizeof(float),
                    cudaMemcpyDeviceToDevice, 0);

    k_wprep<<<32, 256>>>(W, bcv, g, bt, rm, rv,
                         W1, b1, g1, bt1, rm1, rv1,
                         W2, b2, g2, bt2, rm2, rv2);
    k_pre_mma<<<(BB * NN) / 128, 256>>>(xyz, pts);
    k_ball<<<(BB * NN) / 8, 256>>>();
    k_resnet_mma<<<(BB * NN) / 128, 256, smem3>>>(pts, out + in_sizes[0]);
}

// round 17
// speedup vs baseline: 1.4785x; 1.0500x over previous
#include <cuda_runtime.h>
#include <cuda_fp16.h>
#include <cstdint>
#include <cstddef>

#define BB   8
#define NN   4096
#define KK   32
#define DD   64
#define CIN  67
#define MLPC 64
#define P1C  128
#define P2C  64
#define R2   0.04f
#define EPSF 1e-5f

// Scratch (device globals; no allocation allowed)
__device__ __half  Th_g[BB * NN * MLPC];   // fp16 s*(pts·Wd + xyz·Wx + b), 128B rows
__device__ float4  P4_g[BB * NN];          // (x, y, z, ||p||^2)
__device__ float   np_g[BB * NN * MLPC];   // max-pooled features, n-major rows
__device__ float4  sC4_g[MLPC];            // {s*Wx0, s*Wx1, s*Wx2, bt - s*rm}
__device__ float   bs_g[MLPC];             // s*b
__device__ float   t1_g[P1C];              // s1*(b1-rm1)+bt1
__device__ float   t2_g[P2C];              // s2*(b2-rm2)+bt2
__device__ __half  W1f16_g[P1C * P2C];     // s1-folded W1, fp16, [o:128][k:64]
__device__ __half  W2f16_g[P2C * P1C];     // s2-folded W2, fp16, [o2:64][k:128]
__device__ __half  W0f16_g[MLPC * 80];     // s-folded W, fp16, [o:64][k:80 zero-pad]

// ---- mma.sync helpers -----------------------------------------------------
__device__ __forceinline__ uint32_t smem_u32(const void* p) {
    uint32_t a;
    asm("{ .reg .u64 t; cvta.to.shared.u64 t, %1; cvt.u32.u64 %0, t; }"
        : "=r"(a) : "l"(p));
    return a;
}
__device__ __forceinline__ void ldsm_x4(uint32_t& r0, uint32_t& r1,
                                        uint32_t& r2, uint32_t& r3, uint32_t addr) {
    asm volatile("ldmatrix.sync.aligned.m8n8.x4.shared.b16 {%0,%1,%2,%3}, [%4];"
                 : "=r"(r0), "=r"(r1), "=r"(r2), "=r"(r3) : "r"(addr));
}
__device__ __forceinline__ void ldsm_x4_t(uint32_t& r0, uint32_t& r1,
                                          uint32_t& r2, uint32_t& r3, uint32_t addr) {
    asm volatile("ldmatrix.sync.aligned.m8n8.x4.trans.shared.b16 {%0,%1,%2,%3}, [%4];"
                 : "=r"(r0), "=r"(r1), "=r"(r2), "=r"(r3) : "r"(addr));
}
__device__ __forceinline__ void mma16816(float* c, const uint32_t* a,
                                         const uint32_t* b) {
    asm volatile(
        "mma.sync.aligned.m16n8k16.row.col.f32.f16.f16.f32 "
        "{%0,%1,%2,%3}, {%4,%5,%6,%7}, {%8,%9}, {%0,%1,%2,%3};"
        : "+f"(c[0]), "+f"(c[1]), "+f"(c[2]), "+f"(c[3])
        : "r"(a[0]), "r"(a[1]), "r"(a[2]), "r"(a[3]), "r"(b[0]), "r"(b[1]));
}

// ---------------------------------------------------------------------------
// K0: one-time weight prep (folded; fp16 images for mma paths)
// ---------------------------------------------------------------------------
__global__ __launch_bounds__(256) void k_wprep(
    const float* __restrict__ W,   const float* __restrict__ bcv,
    const float* __restrict__ g,   const float* __restrict__ bt,
    const float* __restrict__ rm,  const float* __restrict__ rv,
    const float* __restrict__ W1,  const float* __restrict__ b1,
    const float* __restrict__ g1,  const float* __restrict__ bt1,
    const float* __restrict__ rm1, const float* __restrict__ rv1,
    const float* __restrict__ W2,  const float* __restrict__ b2,
    const float* __restrict__ g2,  const float* __restrict__ bt2,
    const float* __restrict__ rm2, const float* __restrict__ rv2)
{
    int gid = blockIdx.x * 256 + threadIdx.x;

    if (gid < MLPC * 80) {                 // W0 fp16: [o:64][k:80], zero-pad k>=67
        int o = gid / 80, k = gid - o * 80;
        float s = g[o] / sqrtf(rv[o] + EPSF);
        W0f16_g[gid] = __float2half((k < CIN) ? s * W[o * CIN + k] : 0.0f);
    }
    if (gid < P1C * P2C) {                 // W1 fp16: [o:128][k:64]
        int o = gid >> 6, k = gid & 63;
        float s1 = g1[o] / sqrtf(rv1[o] + EPSF);
        W1f16_g[gid] = __float2half(s1 * W1[o * P2C + k]);
    }
    if (gid < P2C * P1C) {                 // W2 fp16: [o2:64][k:128]
        int o2 = gid >> 7, k = gid & 127;
        float s2 = g2[o2] / sqrtf(rv2[o2] + EPSF);
        W2f16_g[gid] = __float2half(s2 * W2[o2 * P1C + k]);
    }
    if (gid < P1C) {
        float s1 = g1[gid] / sqrtf(rv1[gid] + EPSF);
        t1_g[gid] = fmaf(s1, b1[gid] - rm1[gid], bt1[gid]);
    }
    if (gid < P2C) {
        float s2 = g2[gid] / sqrtf(rv2[gid] + EPSF);
        t2_g[gid] = fmaf(s2, b2[gid] - rm2[gid], bt2[gid]);
    }
    if (gid < MLPC) {
        int o = gid;
        float s = g[o] / sqrtf(rv[o] + EPSF);
        bs_g[o] = s * bcv[o];
        sC4_g[o] = make_float4(s * W[o * CIN + 64],
                               s * W[o * CIN + 65],
                               s * W[o * CIN + 66],
                               bt[o] - s * rm[o]);
    }
}

// ---------------------------------------------------------------------------
// K1: Th = X @ W0^T via mma.sync HMMA, A loaded with ldmatrix.trans from
// natural [k][pt] layout (conflict-free staging). 256 thr / 128 pts, grid 256.
// Xh: [k:80][pt:128 pad->136 stride], Wh: [o:64][k:88 stride]. 5 k-steps.
// Warp tile: 16 pt x 64 o. P4 computed from fp32 globals (exact).
// ---------------------------------------------------------------------------
__global__ __launch_bounds__(256) void k_pre_mma(
    const float* __restrict__ xyz, const float* __restrict__ pts)
{
    __shared__ __align__(16) __half Xh[80 * 136];   // 21760 B, [k][pt]
    __shared__ __align__(16) __half Wh[64 * 88];    // 11264 B, [o][k]

    int tid = threadIdx.x, wid = tid >> 5, lane = tid & 31;
    int b  = blockIdx.x >> 5;              // 32 blocks per batch
    int m0 = (blockIdx.x & 31) << 7;       // 128 pts per block

    // zero k-pad rows 67..79 (and their col pads)
    for (int i = tid; i < 13 * 17; i += 256)       // 13 rows x 136 halves = 221 uint4*?
        ((uint4*)(Xh + 67 * 136))[i] = make_uint4(0, 0, 0, 0);

    // W0 copy: [o][80] image -> [o][88] smem rows (16B chunks, coalesced)
    for (int i = tid; i < 64 * 10; i += 256) {
        int r = i / 10, c = i - r * 10;
        *(uint4*)(Wh + r * 88 + c * 8) = *(const uint4*)(W0f16_g + r * 80 + c * 8);
    }

    // X: coalesced channel-major loads, NATURAL-layout fp16 stores [k][pt]
    // (4 consecutive pts per thread = 8B store, conflict-free)
    for (int i = tid; i < CIN * 32; i += 256) {
        int c = i >> 5, j = (i & 31) << 2;
        const float* src = (c < DD) ? &pts[((b << 6) + c) * NN + m0 + j]
                                    : &xyz[(b * 3 + (c - DD)) * NN + m0 + j];
        float4 v = *(const float4*)src;
        __half2 h0 = __floats2half2_rn(v.x, v.y);
        __half2 h1 = __floats2half2_rn(v.z, v.w);
        uint2 pk = make_uint2(*(uint32_t*)&h0, *(uint32_t*)&h1);
        *(uint2*)(Xh + c * 136 + j) = pk;
    }

    // P4 from fp32 globals (exact ball-query inputs)
    if (tid < 128) {
        int m = m0 + tid;
        float x = xyz[(b * 3 + 0) * NN + m];
        float y = xyz[(b * 3 + 1) * NN + m];
        float z = xyz[(b * 3 + 2) * NN + m];
        P4_g[b * NN + m] = make_float4(x, y, z, fmaf(z, z, fmaf(y, y, x * x)));
    }
    __syncthreads();

    uint32_t Xu = smem_u32(Xh);
    uint32_t Wu = smem_u32(Wh);

    int lr = lane & 7, lm = lane >> 3;
    // A via trans: matrix lm covers k-rows (lm>>1)*8, m-cols (lm&1)*8
    int akrow8 = (lm >> 1) * 8, amcol8 = (lm & 1) * 8;
    // B non-trans (as validated in resnet)
    int brow8 = (lm >> 1) * 8, bcol8 = (lm & 1) * 8;

    int pt0 = wid * 16;

    float acc[8][4];
#pragma unroll
    for (int n = 0; n < 8; n++)
#pragma unroll
        for (int q = 0; q < 4; q++) acc[n][q] = 0.0f;

#pragma unroll
    for (int ks = 0; ks < 5; ks++) {
        int k0 = ks * 16;
        uint32_t af[4];
        {
            uint32_t a = Xu + (uint32_t)(((k0 + akrow8 + lr) * 136
                                          + pt0 + amcol8) * 2);
            ldsm_x4_t(af[0], af[1], af[2], af[3], a);
        }
        uint32_t bf[8][2];
#pragma unroll
        for (int nb = 0; nb < 4; nb++) {
            uint32_t a = Wu + (uint32_t)(((nb * 16 + lr + brow8) * 88 + k0 + bcol8) * 2);
            uint32_t r0, r1, r2, r3;
            ldsm_x4(r0, r1, r2, r3, a);
            bf[2 * nb][0] = r0; bf[2 * nb][1] = r1;
            bf[2 * nb + 1][0] = r2; bf[2 * nb + 1][1] = r3;
        }
#pragma unroll
        for (int n = 0; n < 8; n++)
            mma16816(acc[n], af, bf[n]);
    }

    // Epilogue: Th[pt][o] = fp16(acc + bs[o])
    int drow = lane >> 2, dcol = (lane & 3) * 2;
#pragma unroll
    for (int n = 0; n < 8; n++) {
        int col = n * 8 + dcol;
        float ba = __ldg(&bs_g[col]);
        float bbv = __ldg(&bs_g[col + 1]);
        int gmA = b * NN + m0 + pt0 + drow;
        int gmB = gmA + 8;
        __half2 h0 = __floats2half2_rn(acc[n][0] + ba, acc[n][1] + bbv);
        __half2 h1 = __floats2half2_rn(acc[n][2] + ba, acc[n][3] + bbv);
        ((uint32_t*)Th_g)[(size_t)gmA * 32 + (col >> 1)] = *(uint32_t*)&h0;
        ((uint32_t*)Th_g)[(size_t)gmB * 32 + (col >> 1)] = *(uint32_t*)&h1;
    }
}

// ---------------------------------------------------------------------------
// K2: warp-autonomous ball query + fp16 gather-max (unchanged, R8-proven)
// ---------------------------------------------------------------------------
__global__ __launch_bounds__(256) void k_ball()
{
    __shared__ int gi_sh[8][KK];

    int tid  = threadIdx.x;
    int w    = tid >> 5;
    int lane = tid & 31;
    unsigned below = (1u << lane) - 1u;

    int b  = blockIdx.x >> 9;
    int n  = ((blockIdx.x & 511) << 3) + w;
    int bN = b * NN;

    float4 q = P4_g[bN + n];

    int cnt = 0;
#pragma unroll 1
    for (int base = 0; base < NN; base += 64) {
        float4 c0 = __ldg(&P4_g[bN + base + lane]);
        float4 c1 = __ldg(&P4_g[bN + base + 32 + lane]);

        float d0 = q.w + c0.w - 2.0f * fmaf(q.z, c0.z, fmaf(q.y, c0.y, q.x * c0.x));
        float d1 = q.w + c1.w - 2.0f * fmaf(q.z, c1.z, fmaf(q.y, c1.y, q.x * c1.x));

        unsigned m0 = __ballot_sync(0xffffffffu, d0 <= R2);
        unsigned m1 = __ballot_sync(0xffffffffu, d1 <= R2);

        if (d0 <= R2) {
            int pos = cnt + __popc(m0 & below);
            if (pos < KK) gi_sh[w][pos] = base + lane;
        }
        int n0 = __popc(m0);
        if (d1 <= R2) {
            int pos = cnt + n0 + __popc(m1 & below);
            if (pos < KK) gi_sh[w][pos] = base + 32 + lane;
        }
        cnt += n0 + __popc(m1);
        if (cnt >= KK) break;
    }
    __syncwarp();

    int cap   = (cnt < KK) ? cnt : KK;
    int gidx0 = gi_sh[w][0];

    __half2 mx = __float2half2_rn(-65504.0f);
#pragma unroll
    for (int j = 0; j < KK; j++) {
        int gj = (j < cap) ? gi_sh[w][j] : gidx0;
        const __half2* tr = ((const __half2*)Th_g) + (((size_t)(bN + gj)) << 5) + lane;
        mx = __hmax2(mx, __ldg(tr));
    }
    float2 m = __half22float2(mx);

    float4 a0 = sC4_g[2 * lane];
    float4 a1 = sC4_g[2 * lane + 1];
    float u0 = a0.w - fmaf(a0.z, q.z, fmaf(a0.y, q.y, a0.x * q.x));
    float u1 = a1.w - fmaf(a1.z, q.z, fmaf(a1.y, q.y, a1.x * q.x));

    float2 outv = make_float2(fmaxf(m.x + u0, 0.0f), fmaxf(m.y + u1, 0.0f));
    *(float2*)&np_g[((size_t)(bN + n)) * MLPC + 2 * lane] = outv;
}

// ---------------------------------------------------------------------------
// K3: resnet via mma.sync HMMA (unchanged, R15-proven 16.2us)
// ---------------------------------------------------------------------------
__global__ __launch_bounds__(256) void k_resnet_mma(
    const float* __restrict__ pts, float* __restrict__ out)
{
    extern __shared__ __align__(16) __half hsm[];
    __half* Vh  = hsm;            // [128][72]
    __half* W1h = hsm + 9216;     // [128][72]
    __half* X1h = hsm;            // [128][136] (overlaps Vh+W1h)
    __half* W2h = hsm + 18432;    // [64][136]
    __shared__ float t1sh[P1C];
    __shared__ float t2sh[P2C];

    int tid = threadIdx.x, wid = tid >> 5, lane = tid & 31;
    int m0 = blockIdx.x << 7;
    int b  = m0 >> 12;
    int n0 = m0 & (NN - 1);

    if (tid < P1C) t1sh[tid] = t1_g[tid];
    if (tid < P2C) t2sh[tid] = t2_g[tid];

    for (int i = tid; i < 1024; i += 256) {
        int r = i >> 3, c = i & 7;
        *(uint4*)(W1h + r * 72 + c * 8) = *(const uint4*)(W1f16_g + r * 64 + c * 8);
    }
    for (int i = tid; i < 1024; i += 256) {
        int r = i >> 4, c = i & 15;
        *(uint4*)(W2h + r * 136 + c * 8) = *(const uint4*)(W2f16_g + r * 128 + c * 8);
    }
    for (int i = tid; i < 1024; i += 256) {
        int r = i >> 3, c = i & 7;
        const float4* src = (const float4*)(np_g + (size_t)(m0 + r) * MLPC + c * 8);
        float4 x = src[0], y = src[1];
        union { __half2 h2[4]; uint4 u4; } cv;
        cv.h2[0] = __floats2half2_rn(x.x, x.y);
        cv.h2[1] = __floats2half2_rn(x.z, x.w);
        cv.h2[2] = __floats2half2_rn(y.x, y.y);
        cv.h2[3] = __floats2half2_rn(y.z, y.w);
        *(uint4*)(Vh + r * 72 + c * 8) = cv.u4;
    }
    __syncthreads();

    uint32_t Vu  = smem_u32(Vh);
    uint32_t W1u = smem_u32(W1h);
    uint32_t X1u = smem_u32(X1h);
    uint32_t W2u = smem_u32(W2h);

    int lr = lane & 7, lm = lane >> 3;
    int arow8 = (lm & 1) * 8, acol8 = (lm >> 1) * 8;
    int brow8 = (lm >> 1) * 8, bcol8 = (lm & 1) * 8;

    int pt0 = (wid & 3) * 32;
    int o0  = (wid >> 2) * 64;

    float acc[2][8][4];
#pragma unroll
    for (int m = 0; m < 2; m++)
#pragma unroll
        for (int n = 0; n < 8; n++)
#pragma unroll
            for (int q = 0; q < 4; q++) acc[m][n][q] = 0.0f;

#pragma unroll
    for (int ks = 0; ks < 4; ks++) {
        int k0 = ks * 16;
        uint32_t af[2][4];
#pragma unroll
        for (int m = 0; m < 2; m++) {
            uint32_t a = Vu + (uint32_t)(((pt0 + m * 16 + lr + arow8) * 72
                                          + k0 + acol8) * 2);
            ldsm_x4(af[m][0], af[m][1], af[m][2], af[m][3], a);
        }
        uint32_t bf[8][2];
#pragma unroll
        for (int nb = 0; nb < 4; nb++) {
            uint32_t a = W1u + (uint32_t)(((o0 + nb * 16 + lr + brow8) * 72
                                           + k0 + bcol8) * 2);
            uint32_t r0, r1, r2, r3;
            ldsm_x4(r0, r1, r2, r3, a);
            bf[2 * nb][0] = r0; bf[2 * nb][1] = r1;
            bf[2 * nb + 1][0] = r2; bf[2 * nb + 1][1] = r3;
        }
#pragma unroll
        for (int m = 0; m < 2; m++)
#pragma unroll
            for (int n = 0; n < 8; n++)
                mma16816(acc[m][n], af[m], bf[n]);
    }
    __syncthreads();

    int drow = lane >> 2, dcol = (lane & 3) * 2;
#pragma unroll
    for (int m = 0; m < 2; m++)
#pragma unroll
        for (int n = 0; n < 8; n++) {
            int pt  = pt0 + m * 16 + drow;
            int col = o0 + n * 8 + dcol;
            float ta = t1sh[col], tb = t1sh[col + 1];
            __half2 h0 = __floats2half2_rn(fmaxf(acc[m][n][0] + ta, 0.0f),
                                           fmaxf(acc[m][n][1] + tb, 0.0f));
            __half2 h1 = __floats2half2_rn(fmaxf(acc[m][n][2] + ta, 0.0f),
                                           fmaxf(acc[m][n][3] + tb, 0.0f));
            *(uint32_t*)(X1h + pt * 136 + col)       = *(uint32_t*)&h0;
            *(uint32_t*)(X1h + (pt + 8) * 136 + col) = *(uint32_t*)&h1;
        }
    __syncthreads();

    int o20 = (wid >> 2) * 32;
    float acc2[2][4][4];
#pragma unroll
    for (int m = 0; m < 2; m++)
#pragma unroll
        for (int n = 0; n < 4; n++)
#pragma unroll
            for (int q = 0; q < 4; q++) acc2[m][n][q] = 0.0f;

#pragma unroll
    for (int ks = 0; ks < 8; ks++) {
        int k0 = ks * 16;
        uint32_t af[2][4];
#pragma unroll
        for (int m = 0; m < 2; m++) {
            uint32_t a = X1u + (uint32_t)(((pt0 + m * 16 + lr + arow8) * 136
                                           + k0 + acol8) * 2);
            ldsm_x4(af[m][0], af[m][1], af[m][2], af[m][3], a);
        }
        uint32_t bf[4][2];
#pragma unroll
        for (int nb = 0; nb < 2; nb++) {
            uint32_t a = W2u + (uint32_t)(((o20 + nb * 16 + lr + brow8) * 136
                                           + k0 + bcol8) * 2);
            uint32_t r0, r1, r2, r3;
            ldsm_x4(r0, r1, r2, r3, a);
            bf[2 * nb][0] = r0; bf[2 * nb][1] = r1;
            bf[2 * nb + 1][0] = r2; bf[2 * nb + 1][1] = r3;
        }
#pragma unroll
        for (int m = 0; m < 2; m++)
#pragma unroll
            for (int n = 0; n < 4; n++)
                mma16816(acc2[m][n], af[m], bf[n]);
    }

#pragma unroll
    for (int m = 0; m < 2; m++)
#pragma unroll
        for (int n = 0; n < 4; n++) {
            int ptA = pt0 + m * 16 + drow;
            int ptB = ptA + 8;
            int o2  = o20 + n * 8 + dcol;
            float ta = t2sh[o2], tb = t2sh[o2 + 1];
            size_t g0 = ((size_t)(b * P2C + o2)) * NN + n0;
            size_t g1 = ((size_t)(b * P2C + o2 + 1)) * NN + n0;
            out[g0 + ptA] = fmaxf(acc2[m][n][0] + ta + __ldg(&pts[g0 + ptA]), 0.0f);
            out[g1 + ptA] = fmaxf(acc2[m][n][1] + tb + __ldg(&pts[g1 + ptA]), 0.0f);
            out[g0 + ptB] = fmaxf(acc2[m][n][2] + ta + __ldg(&pts[g0 + ptB]), 0.0f);
            out[g1 + ptB] = fmaxf(acc2[m][n][3] + tb + __ldg(&pts[g1 + ptB]), 0.0f);
        }
}

// ---------------------------------------------------------------------------
// Launch
// ---------------------------------------------------------------------------
extern "C" void kernel_launch(void* const* d_in, const int* in_sizes, int n_in,
                              void* d_out, int out_size)
{
    (void)n_in; (void)out_size;

    const float* xyz = (const float*)d_in[0];
    const float* pts = (const float*)d_in[1];
    const float* W   = (const float*)d_in[2];
    const float* bcv = (const float*)d_in[3];
    const float* g   = (const float*)d_in[4];
    const float* bt  = (const float*)d_in[5];
    const float* rm  = (const float*)d_in[6];
    const float* rv  = (const float*)d_in[7];
    const float* W1  = (const float*)d_in[8];
    const float* b1  = (const float*)d_in[9];
    const float* g1  = (const float*)d_in[10];
    const float* bt1 = (const float*)d_in[11];
    const float* rm1 = (const float*)d_in[12];
    const float* rv1 = (const float*)d_in[13];
    const float* W2  = (const float*)d_in[14];
    const float* b2  = (const float*)d_in[15];
    const float* g2  = (const float*)d_in[16];
    const float* bt2 = (const float*)d_in[17];
    const float* rm2 = (const float*)d_in[18];
    const float* rv2 = (const float*)d_in[19];

    float* out = (float*)d_out;

    static const size_t smem3 = 27136 * sizeof(__half);   // 54272 B
    cudaFuncSetAttribute(k_resnet_mma, cudaFuncAttributeMaxDynamicSharedMemorySize,
                         (int)smem3);

    cudaMemcpyAsync(out, xyz, (size_t)in_sizes[0] * sizeof(float),
                    cudaMemcpyDeviceToDevice, 0);

    k_wprep<<<32, 256>>>(W, bcv, g, bt, rm, rv,
                         W1, b1, g1, bt1, rm1, rv1,
                         W2, b2, g2, bt2, rm2, rv2);
    k_pre_mma<<<(BB * NN) / 128, 256>>>(xyz, pts);
    k_ball<<<(BB * NN) / 8, 256>>>();
    k_resnet_mma<<<(BB * NN) / 128, 256, smem3>>>(pts, out + in_sizes[0]);
}